// round 3
// baseline (speedup 1.0000x reference)
#include <cuda_runtime.h>
#include <cuda_bf16.h>

#define N_NODES 50000
#define E_EDGES 1000000
#define DIM     64
#define G_GRAPHS 512
#define O_DIM   16

// Scratch (__device__ globals; no allocation allowed)
__device__ float g_agg [N_NODES * DIM];     // 12.8 MB
__device__ float g_h1  [N_NODES * DIM];     // 12.8 MB
__device__ float g_pool[G_GRAPHS * DIM];    // 128 KB
__device__ int   g_counts[N_NODES];
__device__ int   g_rowptr[N_NODES + 1];
__device__ int   g_cursor[N_NODES];
__device__ int   g_esrc  [E_EDGES];         // 4 MB: src node of each edge, sorted by dst

// ---------------------------------------------------------------------------
// zero counts + pool
// ---------------------------------------------------------------------------
__global__ void zero2_kernel(int* __restrict__ counts, float* __restrict__ pool) {
    int i = blockIdx.x * blockDim.x + threadIdx.x;
    if (i < N_NODES) counts[i] = 0;
    if (i < G_GRAPHS * DIM) pool[i] = 0.f;
}

// ---------------------------------------------------------------------------
// histogram of dst
// ---------------------------------------------------------------------------
__global__ void hist_kernel(const int* __restrict__ dst, int* __restrict__ counts) {
    int e = blockIdx.x * blockDim.x + threadIdx.x;
    if (e < E_EDGES) atomicAdd(&counts[__ldg(&dst[e])], 1);
}

// ---------------------------------------------------------------------------
// single-block exclusive scan of counts -> rowptr (+ cursor copy)
// 1024 threads, each owns a 49-element chunk (1024*49 = 50176 >= 50000)
// ---------------------------------------------------------------------------
__global__ __launch_bounds__(1024) void scan_kernel(const int* __restrict__ counts,
                                                    int* __restrict__ rowptr,
                                                    int* __restrict__ cursor) {
    __shared__ int ssum[1024];
    const int CH = 49;
    int t = threadIdx.x;
    int base = t * CH;

    int s = 0;
    #pragma unroll 7
    for (int i = 0; i < CH; i++) {
        int idx = base + i;
        if (idx < N_NODES) s += __ldg(&counts[idx]);
    }
    ssum[t] = s;
    __syncthreads();

    // Hillis-Steele inclusive scan over 1024 partials
    #pragma unroll
    for (int off = 1; off < 1024; off <<= 1) {
        int v = (t >= off) ? ssum[t - off] : 0;
        __syncthreads();
        ssum[t] += v;
        __syncthreads();
    }

    int run = ssum[t] - s;   // exclusive prefix for this chunk
    #pragma unroll 7
    for (int i = 0; i < CH; i++) {
        int idx = base + i;
        if (idx < N_NODES) {
            rowptr[idx] = run;
            cursor[idx] = run;
            run += __ldg(&counts[idx]);
        }
    }
    if (t == 1023) rowptr[N_NODES] = ssum[1023];   // = E_EDGES
}

// ---------------------------------------------------------------------------
// place edges into dst-sorted order
// ---------------------------------------------------------------------------
__global__ void place_kernel(const int* __restrict__ src, const int* __restrict__ dst,
                             int* __restrict__ cursor, int* __restrict__ esrc) {
    int e = blockIdx.x * blockDim.x + threadIdx.x;
    if (e >= E_EDGES) return;
    int d = __ldg(&dst[e]);
    int p = atomicAdd(&cursor[d], 1);
    esrc[p] = __ldg(&src[e]);
}

// ---------------------------------------------------------------------------
// CSR gather aggregation: warp per node, float2 per lane, register accumulate
// ---------------------------------------------------------------------------
__global__ __launch_bounds__(256) void aggregate_kernel(const float* __restrict__ feat,
                                                        const int*   __restrict__ rowptr,
                                                        const int*   __restrict__ esrc,
                                                        float*       __restrict__ agg) {
    int warp = (blockIdx.x * blockDim.x + threadIdx.x) >> 5;
    int lane = threadIdx.x & 31;
    if (warp >= N_NODES) return;
    int beg = __ldg(&rowptr[warp]);
    int end = __ldg(&rowptr[warp + 1]);

    float2 a0 = make_float2(0.f, 0.f);
    float2 a1 = make_float2(0.f, 0.f);
    const float2* f2 = (const float2*)feat;

    int e = beg;
    for (; e + 1 < end; e += 2) {
        int s0 = __ldg(&esrc[e]);
        int s1 = __ldg(&esrc[e + 1]);
        float2 v0 = __ldg(&f2[s0 * 32 + lane]);
        float2 v1 = __ldg(&f2[s1 * 32 + lane]);
        a0.x += v0.x; a0.y += v0.y;
        a1.x += v1.x; a1.y += v1.y;
    }
    if (e < end) {
        int s0 = __ldg(&esrc[e]);
        float2 v0 = __ldg(&f2[s0 * 32 + lane]);
        a0.x += v0.x; a0.y += v0.y;
    }
    a0.x += a1.x; a0.y += a1.y;
    ((float2*)agg)[warp * 32 + lane] = a0;
}

// ---------------------------------------------------------------------------
// fused SAGE GEMM:  out = relu( agg @ Wl + x @ Wr + b )
// 128 rows/block, 256 threads, 4 rows x 8 cols per thread.
// POOL=1: instead of storing rows, red.add them into pool[batch[row]].
// Dynamic smem: sWl[4096] sWr[4096] sA[128*66] sX[128*66]  (= 100,352 B)
// ---------------------------------------------------------------------------
template<int POOL>
__global__ __launch_bounds__(256) void sage_gemm_kernel(
        const float* __restrict__ agg, const float* __restrict__ xin,
        const float* __restrict__ Wl,  const float* __restrict__ Wr,
        const float* __restrict__ b,   float* __restrict__ out,
        const int* __restrict__ batch, float* __restrict__ pool, int n) {
    extern __shared__ float smem[];
    float* sWl = smem;                       // 64*64
    float* sWr = smem + 4096;                // 64*64
    float* sA  = smem + 8192;                // 128*66
    float* sX  = sA + 128 * 66;              // 128*66
    __shared__ float sB[64];

    int tid = threadIdx.x;

    for (int i = tid; i < 1024; i += 256) {
        ((float4*)sWl)[i] = __ldg(&((const float4*)Wl)[i]);
        ((float4*)sWr)[i] = __ldg(&((const float4*)Wr)[i]);
    }
    if (tid < 64) sB[tid] = __ldg(&b[tid]);

    int row0 = blockIdx.x * 128;
    // tile loads: 128 rows x 32 float2 per array
    for (int i = tid; i < 4096; i += 256) {
        int r  = i >> 5;
        int c2 = i & 31;
        int gr = row0 + r;
        float2 va = make_float2(0.f, 0.f), vx = va;
        if (gr < n) {
            va = __ldg(&((const float2*)agg)[gr * 32 + c2]);
            vx = __ldg(&((const float2*)xin)[gr * 32 + c2]);
        }
        *(float2*)&sA[r * 66 + c2 * 2] = va;
        *(float2*)&sX[r * 66 + c2 * 2] = vx;
    }
    __syncthreads();

    int cg = (tid & 7) * 8;
    int rg = tid >> 3;          // 0..31; rows rg, rg+32, rg+64, rg+96

    float acc[4][8];
    #pragma unroll
    for (int jj = 0; jj < 4; jj++)
        #pragma unroll
        for (int j = 0; j < 8; j++) acc[jj][j] = sB[cg + j];

    #pragma unroll
    for (int k = 0; k < 64; k++) {
        float4 wl0 = *(const float4*)&sWl[k * 64 + cg];
        float4 wl1 = *(const float4*)&sWl[k * 64 + cg + 4];
        float4 wr0 = *(const float4*)&sWr[k * 64 + cg];
        float4 wr1 = *(const float4*)&sWr[k * 64 + cg + 4];
        #pragma unroll
        for (int jj = 0; jj < 4; jj++) {
            int r = rg + jj * 32;
            float a = sA[r * 66 + k];
            float h = sX[r * 66 + k];
            acc[jj][0] += a * wl0.x + h * wr0.x;
            acc[jj][1] += a * wl0.y + h * wr0.y;
            acc[jj][2] += a * wl0.z + h * wr0.z;
            acc[jj][3] += a * wl0.w + h * wr0.w;
            acc[jj][4] += a * wl1.x + h * wr1.x;
            acc[jj][5] += a * wl1.y + h * wr1.y;
            acc[jj][6] += a * wl1.z + h * wr1.z;
            acc[jj][7] += a * wl1.w + h * wr1.w;
        }
    }

    #pragma unroll
    for (int jj = 0; jj < 4; jj++) {
        int gr = row0 + rg + jj * 32;
        if (gr >= n) continue;
        float4 o0, o1;
        o0.x = fmaxf(acc[jj][0], 0.f); o0.y = fmaxf(acc[jj][1], 0.f);
        o0.z = fmaxf(acc[jj][2], 0.f); o0.w = fmaxf(acc[jj][3], 0.f);
        o1.x = fmaxf(acc[jj][4], 0.f); o1.y = fmaxf(acc[jj][5], 0.f);
        o1.z = fmaxf(acc[jj][6], 0.f); o1.w = fmaxf(acc[jj][7], 0.f);
        if (POOL) {
            int bg = __ldg(&batch[gr]);
            float* p = &pool[bg * 64 + cg];
            asm volatile("red.global.add.v4.f32 [%0], {%1,%2,%3,%4};"
                         :: "l"(p), "f"(o0.x), "f"(o0.y), "f"(o0.z), "f"(o0.w) : "memory");
            asm volatile("red.global.add.v4.f32 [%0], {%1,%2,%3,%4};"
                         :: "l"(p + 4), "f"(o1.x), "f"(o1.y), "f"(o1.z), "f"(o1.w) : "memory");
        } else {
            float4* op = (float4*)&out[gr * 64 + cg];
            op[0] = o0;
            op[1] = o1;
        }
    }
}

// ---------------------------------------------------------------------------
// head:  out = pool @ Wo + bo     [512,64] @ [64,16] -> [512,16]
// ---------------------------------------------------------------------------
__global__ void head_kernel(const float* __restrict__ pool,
                            const float* __restrict__ Wo,
                            const float* __restrict__ bo,
                            float*       __restrict__ out) {
    __shared__ float sW[64 * 16];
    __shared__ float sb[16];
    int tid = threadIdx.x;
    for (int i = tid; i < 64 * 16; i += 256) sW[i] = __ldg(&Wo[i]);
    if (tid < 16) sb[tid] = __ldg(&bo[tid]);
    __syncthreads();

    int t = blockIdx.x * blockDim.x + tid;
    if (t >= G_GRAPHS * O_DIM) return;
    int row = t >> 4;
    int col = t & 15;
    float acc = sb[col];
    const float* pr = &pool[row * 64];
    #pragma unroll
    for (int k = 0; k < 64; k++) acc += pr[k] * sW[k * 16 + col];
    out[row * O_DIM + col] = acc;
}

// ---------------------------------------------------------------------------
// launch
// ---------------------------------------------------------------------------
extern "C" void kernel_launch(void* const* d_in, const int* in_sizes, int n_in,
                              void* d_out, int out_size) {
    const float* x   = (const float*)d_in[0];
    const int*   ei  = (const int*)  d_in[1];
    const int*   bat = (const int*)  d_in[2];
    const float* Wl1 = (const float*)d_in[3];
    const float* Wr1 = (const float*)d_in[4];
    const float* b1  = (const float*)d_in[5];
    const float* Wl2 = (const float*)d_in[6];
    const float* Wr2 = (const float*)d_in[7];
    const float* b2  = (const float*)d_in[8];
    const float* Wo  = (const float*)d_in[9];
    const float* bo  = (const float*)d_in[10];
    float* out = (float*)d_out;

    const int* src = ei;
    const int* dst = ei + E_EDGES;

    float *agg, *h1, *pool;
    int *counts, *rowptr, *cursor, *esrc;
    cudaGetSymbolAddress((void**)&agg,    g_agg);
    cudaGetSymbolAddress((void**)&h1,     g_h1);
    cudaGetSymbolAddress((void**)&pool,   g_pool);
    cudaGetSymbolAddress((void**)&counts, g_counts);
    cudaGetSymbolAddress((void**)&rowptr, g_rowptr);
    cudaGetSymbolAddress((void**)&cursor, g_cursor);
    cudaGetSymbolAddress((void**)&esrc,   g_esrc);

    static bool attr_done = false;
    const int gemmSmem = (8192 + 2 * 128 * 66) * sizeof(float);   // 100,352 B
    if (!attr_done) {
        cudaFuncSetAttribute(sage_gemm_kernel<0>,
                             cudaFuncAttributeMaxDynamicSharedMemorySize, gemmSmem);
        cudaFuncSetAttribute(sage_gemm_kernel<1>,
                             cudaFuncAttributeMaxDynamicSharedMemorySize, gemmSmem);
        attr_done = true;
    }

    const int eBlocks   = (E_EDGES + 255) / 256;       // 3907
    const int aggBlocks = (N_NODES * 32 + 255) / 256;  // 6250 (warp per node)
    const int gemmBlocks = (N_NODES + 127) / 128;      // 391

    // ---- build CSR (once; reused by both layers) + zero pool ----
    zero2_kernel<<<(N_NODES + 255) / 256, 256>>>(counts, pool);
    hist_kernel<<<eBlocks, 256>>>(dst, counts);
    scan_kernel<<<1, 1024>>>(counts, rowptr, cursor);
    place_kernel<<<eBlocks, 256>>>(src, dst, cursor, esrc);

    // ---- layer 1 ----
    aggregate_kernel<<<aggBlocks, 256>>>(x, rowptr, esrc, agg);
    sage_gemm_kernel<0><<<gemmBlocks, 256, gemmSmem>>>(agg, x, Wl1, Wr1, b1,
                                                       h1, nullptr, nullptr, N_NODES);

    // ---- layer 2 (+ fused global add pool) ----
    aggregate_kernel<<<aggBlocks, 256>>>(h1, rowptr, esrc, agg);
    sage_gemm_kernel<1><<<gemmBlocks, 256, gemmSmem>>>(agg, h1, Wl2, Wr2, b2,
                                                       nullptr, bat, pool, N_NODES);

    // ---- head ----
    head_kernel<<<(G_GRAPHS * O_DIM + 255) / 256, 256>>>(pool, Wo, bo, out);
}

// round 4
// speedup vs baseline: 1.2478x; 1.2478x over previous
#include <cuda_runtime.h>
#include <cuda_bf16.h>

#define N_NODES 50000
#define E_EDGES 1000000
#define DIM     64
#define G_GRAPHS 512
#define O_DIM   16

// Scratch (__device__ globals; no allocation allowed)
__device__ float g_p   [N_NODES * DIM];     // 12.8 MB  projected (Wl) features
__device__ float g_xr  [N_NODES * DIM];     // 12.8 MB  root-path (Wr) features
__device__ float g_h1  [N_NODES * DIM];     // 12.8 MB  layer-1 output
__device__ float g_pool[G_GRAPHS * DIM];    // 128 KB
__device__ int   g_counts[N_NODES];
__device__ int   g_rowptr[N_NODES + 1];
__device__ int   g_cursor[N_NODES];
__device__ int   g_esrc  [E_EDGES];         // src node per edge, sorted by dst

// ---------------------------------------------------------------------------
// zero counts + pool
// ---------------------------------------------------------------------------
__global__ void zero2_kernel(int* __restrict__ counts, float* __restrict__ pool) {
    int i = blockIdx.x * blockDim.x + threadIdx.x;
    if (i < N_NODES) counts[i] = 0;
    if (i < G_GRAPHS * DIM) pool[i] = 0.f;
}

// ---------------------------------------------------------------------------
// histogram of dst (4 edges / thread for ILP)
// ---------------------------------------------------------------------------
__global__ void hist_kernel(const int* __restrict__ dst, int* __restrict__ counts) {
    int e = (blockIdx.x * blockDim.x + threadIdx.x) * 4;
    if (e + 3 >= E_EDGES) {
        for (; e < E_EDGES; e++) atomicAdd(&counts[__ldg(&dst[e])], 1);
        return;
    }
    int d0 = __ldg(&dst[e]);
    int d1 = __ldg(&dst[e + 1]);
    int d2 = __ldg(&dst[e + 2]);
    int d3 = __ldg(&dst[e + 3]);
    atomicAdd(&counts[d0], 1);
    atomicAdd(&counts[d1], 1);
    atomicAdd(&counts[d2], 1);
    atomicAdd(&counts[d3], 1);
}

// ---------------------------------------------------------------------------
// exclusive scan of counts -> rowptr (+ cursor) ; warp-shuffle based, 2 syncs
// 1024 threads x 49-element chunks (50176 >= 50000)
// ---------------------------------------------------------------------------
__global__ __launch_bounds__(1024) void scan_kernel(const int* __restrict__ counts,
                                                    int* __restrict__ rowptr,
                                                    int* __restrict__ cursor) {
    __shared__ int warpsum[32];
    const int CH = 49;
    int t = threadIdx.x;
    int base = t * CH;
    int lane = t & 31, wid = t >> 5;

    int s = 0;
    #pragma unroll 7
    for (int i = 0; i < CH; i++) {
        int idx = base + i;
        if (idx < N_NODES) s += __ldg(&counts[idx]);
    }
    // warp inclusive scan
    int v = s;
    #pragma unroll
    for (int off = 1; off < 32; off <<= 1) {
        int u = __shfl_up_sync(0xffffffffu, v, off);
        if (lane >= off) v += u;
    }
    if (lane == 31) warpsum[wid] = v;
    __syncthreads();
    if (wid == 0) {
        int w = warpsum[lane];
        #pragma unroll
        for (int off = 1; off < 32; off <<= 1) {
            int u = __shfl_up_sync(0xffffffffu, w, off);
            if (lane >= off) w += u;
        }
        warpsum[lane] = w;
    }
    __syncthreads();

    int run = v - s + (wid > 0 ? warpsum[wid - 1] : 0);   // exclusive prefix
    #pragma unroll 7
    for (int i = 0; i < CH; i++) {
        int idx = base + i;
        if (idx < N_NODES) {
            rowptr[idx] = run;
            cursor[idx] = run;
            run += __ldg(&counts[idx]);
        }
    }
    if (t == 1023) rowptr[N_NODES] = E_EDGES;
}

// ---------------------------------------------------------------------------
// place edges into dst-sorted order (4 edges / thread)
// ---------------------------------------------------------------------------
__global__ void place_kernel(const int* __restrict__ src, const int* __restrict__ dst,
                             int* __restrict__ cursor, int* __restrict__ esrc) {
    int e = (blockIdx.x * blockDim.x + threadIdx.x) * 4;
    #pragma unroll
    for (int j = 0; j < 4; j++) {
        int ee = e + j;
        if (ee < E_EDGES) {
            int d = __ldg(&dst[ee]);
            int p = atomicAdd(&cursor[d], 1);
            esrc[p] = __ldg(&src[ee]);
        }
    }
}

// ---------------------------------------------------------------------------
// dual GEMM:  p = in @ Wl     xr = in @ Wr + b      (in: [n,64])
// block: 128 rows x 64 cols, 256 threads, thread tile 8 rows x 4 cols x 2 mats
// ---------------------------------------------------------------------------
__global__ __launch_bounds__(256) void dual_gemm_kernel(
        const float* __restrict__ in, const float* __restrict__ Wl,
        const float* __restrict__ Wr, const float* __restrict__ b,
        float* __restrict__ p, float* __restrict__ xr, int n) {
    extern __shared__ float sm[];
    float* sIn = sm;                    // 128 * 68
    float* sWl = sm + 128 * 68;         // 64 * 64
    float* sWr = sWl + 4096;            // 64 * 64
    __shared__ float sB[64];

    int tid = threadIdx.x;
    for (int i = tid; i < 1024; i += 256) {
        ((float4*)sWl)[i] = __ldg(&((const float4*)Wl)[i]);
        ((float4*)sWr)[i] = __ldg(&((const float4*)Wr)[i]);
    }
    if (tid < 64) sB[tid] = __ldg(&b[tid]);

    int row0 = blockIdx.x * 128;
    for (int i = tid; i < 2048; i += 256) {      // 128 rows x 16 float4
        int r = i >> 4, c4 = i & 15;
        float4 v = make_float4(0.f, 0.f, 0.f, 0.f);
        int gr = row0 + r;
        if (gr < n) v = __ldg(&((const float4*)in)[gr * 16 + c4]);
        *(float4*)&sIn[r * 68 + c4 * 4] = v;
    }
    __syncthreads();

    int tx = tid & 15, ty = tid >> 4;
    int cg = tx * 4;

    float accL[8][4], accR[8][4];
    #pragma unroll
    for (int i = 0; i < 8; i++) {
        #pragma unroll
        for (int j = 0; j < 4; j++) { accL[i][j] = 0.f; accR[i][j] = sB[cg + j]; }
    }

    #pragma unroll 8
    for (int k = 0; k < 64; k++) {
        float4 wl = *(const float4*)&sWl[k * 64 + cg];
        float4 wr = *(const float4*)&sWr[k * 64 + cg];
        #pragma unroll
        for (int i = 0; i < 8; i++) {
            float a = sIn[(ty + 16 * i) * 68 + k];
            accL[i][0] += a * wl.x; accL[i][1] += a * wl.y;
            accL[i][2] += a * wl.z; accL[i][3] += a * wl.w;
            accR[i][0] += a * wr.x; accR[i][1] += a * wr.y;
            accR[i][2] += a * wr.z; accR[i][3] += a * wr.w;
        }
    }

    #pragma unroll
    for (int i = 0; i < 8; i++) {
        int gr = row0 + ty + 16 * i;
        if (gr < n) {
            *(float4*)&p [gr * 64 + cg] = *(float4*)accL[i];
            *(float4*)&xr[gr * 64 + cg] = *(float4*)accR[i];
        }
    }
}

// ---------------------------------------------------------------------------
// fused aggregation + epilogue:
//   POOL=0:  out[node] = relu( segsum(p) + xr[node] )
//   POOL=1:  pool[batch[node]] += relu( segsum(p) + xr[node] )   (red.v4)
// 16 lanes per node (float4/lane), 4-edge unroll for MLP
// ---------------------------------------------------------------------------
template<int POOL>
__global__ __launch_bounds__(256) void agg_epi_kernel(
        const float* __restrict__ p,  const float* __restrict__ xr,
        const int* __restrict__ rowptr, const int* __restrict__ esrc,
        float* __restrict__ out, const int* __restrict__ batch,
        float* __restrict__ pool) {
    int node = (blockIdx.x * blockDim.x + threadIdx.x) >> 4;
    int lane = threadIdx.x & 15;
    if (node >= N_NODES) return;
    int beg = __ldg(&rowptr[node]);
    int end = __ldg(&rowptr[node + 1]);

    const float4* f4 = (const float4*)p;
    float4 a0 = make_float4(0.f, 0.f, 0.f, 0.f);
    float4 a1 = a0, a2 = a0, a3 = a0;

    int e = beg;
    for (; e + 3 < end; e += 4) {
        int s0 = __ldg(&esrc[e]);
        int s1 = __ldg(&esrc[e + 1]);
        int s2 = __ldg(&esrc[e + 2]);
        int s3 = __ldg(&esrc[e + 3]);
        float4 v0 = __ldg(&f4[s0 * 16 + lane]);
        float4 v1 = __ldg(&f4[s1 * 16 + lane]);
        float4 v2 = __ldg(&f4[s2 * 16 + lane]);
        float4 v3 = __ldg(&f4[s3 * 16 + lane]);
        a0.x += v0.x; a0.y += v0.y; a0.z += v0.z; a0.w += v0.w;
        a1.x += v1.x; a1.y += v1.y; a1.z += v1.z; a1.w += v1.w;
        a2.x += v2.x; a2.y += v2.y; a2.z += v2.z; a2.w += v2.w;
        a3.x += v3.x; a3.y += v3.y; a3.z += v3.z; a3.w += v3.w;
    }
    for (; e < end; e++) {
        int s0 = __ldg(&esrc[e]);
        float4 v0 = __ldg(&f4[s0 * 16 + lane]);
        a0.x += v0.x; a0.y += v0.y; a0.z += v0.z; a0.w += v0.w;
    }
    a0.x += a1.x + a2.x + a3.x;
    a0.y += a1.y + a2.y + a3.y;
    a0.z += a1.z + a2.z + a3.z;
    a0.w += a1.w + a2.w + a3.w;

    float4 r = __ldg(&((const float4*)xr)[node * 16 + lane]);
    float4 o;
    o.x = fmaxf(a0.x + r.x, 0.f);
    o.y = fmaxf(a0.y + r.y, 0.f);
    o.z = fmaxf(a0.z + r.z, 0.f);
    o.w = fmaxf(a0.w + r.w, 0.f);

    if (POOL) {
        int bg = __ldg(&batch[node]);
        float* pp = &pool[bg * 64 + lane * 4];
        asm volatile("red.global.add.v4.f32 [%0], {%1,%2,%3,%4};"
                     :: "l"(pp), "f"(o.x), "f"(o.y), "f"(o.z), "f"(o.w) : "memory");
    } else {
        ((float4*)out)[node * 16 + lane] = o;
    }
}

// ---------------------------------------------------------------------------
// head:  out = pool @ Wo + bo     [512,64] @ [64,16] -> [512,16]
// ---------------------------------------------------------------------------
__global__ void head_kernel(const float* __restrict__ pool,
                            const float* __restrict__ Wo,
                            const float* __restrict__ bo,
                            float*       __restrict__ out) {
    __shared__ float sW[64 * 16];
    __shared__ float sb[16];
    int tid = threadIdx.x;
    for (int i = tid; i < 64 * 16; i += 256) sW[i] = __ldg(&Wo[i]);
    if (tid < 16) sb[tid] = __ldg(&bo[tid]);
    __syncthreads();

    int t = blockIdx.x * blockDim.x + tid;
    if (t >= G_GRAPHS * O_DIM) return;
    int row = t >> 4;
    int col = t & 15;
    float acc = sb[col];
    const float* pr = &pool[row * 64];
    #pragma unroll
    for (int k = 0; k < 64; k++) acc += pr[k] * sW[k * 16 + col];
    out[row * O_DIM + col] = acc;
}

// ---------------------------------------------------------------------------
// launch
// ---------------------------------------------------------------------------
extern "C" void kernel_launch(void* const* d_in, const int* in_sizes, int n_in,
                              void* d_out, int out_size) {
    const float* x   = (const float*)d_in[0];
    const int*   ei  = (const int*)  d_in[1];
    const int*   bat = (const int*)  d_in[2];
    const float* Wl1 = (const float*)d_in[3];
    const float* Wr1 = (const float*)d_in[4];
    const float* b1  = (const float*)d_in[5];
    const float* Wl2 = (const float*)d_in[6];
    const float* Wr2 = (const float*)d_in[7];
    const float* b2  = (const float*)d_in[8];
    const float* Wo  = (const float*)d_in[9];
    const float* bo  = (const float*)d_in[10];
    float* out = (float*)d_out;

    const int* src = ei;
    const int* dst = ei + E_EDGES;

    float *p, *xr, *h1, *pool;
    int *counts, *rowptr, *cursor, *esrc;
    cudaGetSymbolAddress((void**)&p,      g_p);
    cudaGetSymbolAddress((void**)&xr,     g_xr);
    cudaGetSymbolAddress((void**)&h1,     g_h1);
    cudaGetSymbolAddress((void**)&pool,   g_pool);
    cudaGetSymbolAddress((void**)&counts, g_counts);
    cudaGetSymbolAddress((void**)&rowptr, g_rowptr);
    cudaGetSymbolAddress((void**)&cursor, g_cursor);
    cudaGetSymbolAddress((void**)&esrc,   g_esrc);

    static cudaStream_t s1 = nullptr;
    static cudaEvent_t evF = nullptr, evJ = nullptr;
    static bool attr_done = false;
    const int gemmSmem = (128 * 68 + 2 * 4096) * sizeof(float);   // 67,584 B
    if (!attr_done) {
        cudaFuncSetAttribute(dual_gemm_kernel,
                             cudaFuncAttributeMaxDynamicSharedMemorySize, gemmSmem);
        cudaStreamCreateWithFlags(&s1, cudaStreamNonBlocking);
        cudaEventCreateWithFlags(&evF, cudaEventDisableTiming);
        cudaEventCreateWithFlags(&evJ, cudaEventDisableTiming);
        attr_done = true;
    }

    const int e4Blocks  = (E_EDGES / 4 + 255) / 256;    // 977
    const int aggBlocks = (N_NODES * 16 + 255) / 256;   // 3125
    const int gemmBlocks = (N_NODES + 127) / 128;       // 391

    // fork: GEMM-1 (no graph dependency) runs concurrently with CSR build
    cudaEventRecord(evF, 0);
    cudaStreamWaitEvent(s1, evF, 0);

    // stream 0: CSR build + pool zero
    zero2_kernel<<<(N_NODES + 255) / 256, 256>>>(counts, pool);
    hist_kernel<<<e4Blocks, 256>>>(dst, counts);
    scan_kernel<<<1, 1024>>>(counts, rowptr, cursor);
    place_kernel<<<e4Blocks, 256>>>(src, dst, cursor, esrc);

    // stream 1: layer-1 projections  p = x@Wl1, xr = x@Wr1 + b1
    dual_gemm_kernel<<<gemmBlocks, 256, gemmSmem, s1>>>(x, Wl1, Wr1, b1, p, xr, N_NODES);
    cudaEventRecord(evJ, s1);
    cudaStreamWaitEvent(0, evJ, 0);

    // layer 1 aggregate + epilogue -> h1
    agg_epi_kernel<0><<<aggBlocks, 256>>>(p, xr, rowptr, esrc, h1, nullptr, nullptr);

    // layer 2 projections + aggregate (+ fused global add pool)
    dual_gemm_kernel<<<gemmBlocks, 256, gemmSmem>>>(h1, Wl2, Wr2, b2, p, xr, N_NODES);
    agg_epi_kernel<1><<<aggBlocks, 256>>>(p, xr, rowptr, esrc, nullptr, bat, pool);

    // head
    head_kernel<<<(G_GRAPHS * O_DIM + 255) / 256, 256>>>(pool, Wo, bo, out);
}